// round 8
// baseline (speedup 1.0000x reference)
#include <cuda_runtime.h>
#include <stdint.h>

#define NEGF (-1e30f)

constexpr int T = 1024;
constexpr int B = 32;
constexpr int C = 96;
constexpr int W = 16;   // beam width
constexpr int P = 4;    // top paths
constexpr int S = 21;   // top lp columns kept per (b,t); staircase needs i <= 20

// per (b,t): top-S non-blank lp columns as packed keys (ord(lp)<<7 | (127-c)), desc
__device__ unsigned long long g_sorted[(size_t)B * T * S];

// ---------- key helpers ----------
__device__ __forceinline__ unsigned ford(float f) {
    unsigned u = __float_as_uint(f);
    return (u & 0x80000000u) ? ~u : (u | 0x80000000u);
}
__device__ __forceinline__ float funord(unsigned ord) {
    unsigned u = (ord & 0x80000000u) ? (ord ^ 0x80000000u) : ~ord;
    return __uint_as_float(u);
}
// larger score wins; ties -> lower global index wins (matches jax.lax.top_k)
__device__ __forceinline__ unsigned long long make_key(float f, int idx) {
    return ((unsigned long long)ford(f) << 11) | (unsigned long long)(2047 - idx);
}
__device__ __forceinline__ int key_idx(unsigned long long k) { return 2047 - (int)(k & 2047ULL); }
__device__ __forceinline__ float key_score(unsigned long long k) { return funord((unsigned)(k >> 11)); }

__device__ __forceinline__ float lae(float a, float b) {   // jnp.logaddexp
    float m = fmaxf(a, b);
    float d = fabsf(a - b);
    return m + log1pf(expf(-d));
}

// descending bitonic sort of 32 keys across a warp (lane = index). Proven in R2.
__device__ __forceinline__ void sort32_desc(unsigned long long& v, int lane) {
    #pragma unroll
    for (int k2 = 2; k2 <= 32; k2 <<= 1) {
        #pragma unroll
        for (int j = k2 >> 1; j > 0; j >>= 1) {
            unsigned long long o = __shfl_xor_sync(0xffffffffu, v, j);
            bool takemax = ((lane & k2) == 0) == ((lane & j) == 0);
            bool bigger  = v > o;
            v = (takemax == bigger) ? v : o;
        }
    }
}

// top-16 (sorted desc, lanes 0-15) of two lists whose top-16 live sorted-desc
// in lanes 0-15 of a and b. Mirror-max + 4-pass bitonic clean. Proven in R4/R5.
__device__ __forceinline__ unsigned long long merge_top16(
    unsigned long long a, unsigned long long b, int lane) {
    unsigned long long brev = __shfl_sync(0xffffffffu, b, (15 - lane) & 31);
    unsigned long long v = (a > brev) ? a : brev;
    #pragma unroll
    for (int j = 8; j > 0; j >>= 1) {
        unsigned long long o = __shfl_xor_sync(0xffffffffu, v, j);
        bool takemax = ((lane & j) == 0);
        bool bigger  = v > o;
        v = (takemax == bigger) ? v : o;
    }
    return v;   // lanes 0-15 valid
}

// ============================================================================
// Kernel 1: per-(b,t) bitonic sort of non-blank lp columns, keep top-S.
// ============================================================================
__global__ __launch_bounds__(256)
void presort_kernel(const float* __restrict__ data)   // [T, B, C]
{
    int warp = (blockIdx.x * blockDim.x + threadIdx.x) >> 5;
    if (warp >= B * T) return;
    int b = warp / T, t = warp - b * T;
    int lane = threadIdx.x & 31;

    const float* row = data + ((size_t)t * B + b) * C;
    unsigned long long k[4];
    #pragma unroll
    for (int r = 0; r < 4; ++r) {
        int c = r * 32 + lane;
        if (c >= 1 && c < C)
            k[r] = ((unsigned long long)ford(row[c]) << 7) | (unsigned long long)(127 - c);
        else
            k[r] = 0ULL;
    }
    #pragma unroll
    for (int k2 = 2; k2 <= 128; k2 <<= 1) {
        #pragma unroll
        for (int j = 64; j > 0; j >>= 1) {
            if (j >= k2) continue;
            if (j >= 32) {
                int rj = j >> 5;
                #pragma unroll
                for (int r = 0; r < 4; ++r) {
                    if ((r & rj) == 0) {
                        int pr = r | rj;
                        bool desc = (((r * 32) & k2) == 0);
                        unsigned long long a = k[r], c2 = k[pr];
                        unsigned long long mx = a > c2 ? a : c2;
                        unsigned long long mn = a > c2 ? c2 : a;
                        k[r]  = desc ? mx : mn;
                        k[pr] = desc ? mn : mx;
                    }
                }
            } else {
                #pragma unroll
                for (int r = 0; r < 4; ++r) {
                    unsigned long long o = __shfl_xor_sync(0xffffffffu, k[r], j);
                    int e = r * 32 + lane;
                    bool takemax = ((e & k2) == 0) == ((lane & j) == 0);
                    bool bigger  = k[r] > o;
                    k[r] = (takemax == bigger) ? k[r] : o;
                }
            }
        }
    }
    if (lane < S)
        g_sorted[((size_t)b * T + t) * S + lane] = k[0];
}

// ============================================================================
// Kernel 2: ONE WARP per batch element. Zero barriers, register-resident state.
// Staircase candidate pool (78 ext cells + 16 stay + 16 rep) sorted exactly.
// ============================================================================
__global__ __launch_bounds__(32, 1)
void ctc_beam_kernel(const float* __restrict__ data,      // [T, B, C]
                     const int*   __restrict__ data_len,  // [B]
                     float*       __restrict__ out)
{
    const int b    = blockIdx.x;
    const int lane = threadIdx.x;
    const int len  = data_len[b];
    const unsigned FULL = 0xffffffffu;

    __shared__ float sh_lp[2][C];
    __shared__ unsigned long long sh_srt[2][S];
    __shared__ unsigned short s_bp[T][W];                 // (parent<<8)|sym, 0xFF = stay
    __shared__ int   s_selslot[P], s_sellen[P];
    __shared__ float s_selscore[P];

    // ---- static pool map: slot s = r*32+lane -> (w, i), staircase i <= 20/(w+1)
    // counts per row: {21,11,7,6,5,4,3,3,3,3,2,2,2,2,2,2} -> 78 cells
    int pw[3], pi[3];
    {
        const int pref[17] = {0,21,32,39,45,50,54,57,60,63,66,68,70,72,74,76,78};
        #pragma unroll
        for (int r = 0; r < 3; ++r) {
            int s = r * 32 + lane;
            int w = -1, i = 0;
            #pragma unroll
            for (int ww = 0; ww < 16; ++ww)
                if (s >= pref[ww] && s < pref[ww + 1]) { w = ww; i = s - pref[ww]; }
            pw[r] = w; pi[r] = i;
        }
    }

    // ---- prologue: row 0 into buf 0
    {
        const float* row0 = data + (size_t)b * C;
        sh_lp[0][lane]      = row0[lane];
        sh_lp[0][32 + lane] = row0[32 + lane];
        sh_lp[0][64 + lane] = row0[64 + lane];
        if (lane < S) sh_srt[0][lane] = g_sorted[((size_t)b * T) * S + lane];
    }
    __syncwarp();

    // ---- register beam state (lanes 0-15 live; high lanes pinned dead)
    float pb   = (lane == 0) ? 0.0f : NEGF;
    float pnb  = NEGF;
    float ptot = lae(pb, pnb);
    int   llen = 0, llast = -1;

    for (int t = 0; t < len; ++t) {
        const int buf = t & 1, nb = buf ^ 1;

        // issue loads for row t+1 (parked ~25 shuffle-passes later)
        float f0 = 0.f, f1 = 0.f, f2 = 0.f; unsigned long long sv = 0ULL;
        if (t + 1 < T) {
            const float* rown = data + (size_t)((t + 1) * B + b) * C;
            f0 = rown[lane]; f1 = rown[32 + lane]; f2 = rown[64 + lane];
            if (lane < S) sv = g_sorted[((size_t)b * T + t + 1) * S + lane];
        }

        // ---- build stay / repeat candidates (lane = beam, SIMD; one lae chain)
        float lp0  = sh_lp[buf][0];
        int   lidx = (llen > 0) ? llast : 0;
        lidx = (lidx >= 0 && lidx < C) ? lidx : 0;        // high-lane safety
        float lpl  = sh_lp[buf][lidx];
        float spb  = ptot + lp0;
        float spnb = (llen > 0) ? (pnb + lpl) : NEGF;
        unsigned long long staykey = make_key(lae(spb, spnb), lane);
        unsigned long long repkey  = (llen > 0)
            ? make_key(pb + lpl, W + lane * C + llast) : 0ULL;

        // ---- assemble pool: regs 0-2 = staircase ext cells, reg 3 = stay|rep
        unsigned long long k0, k1, k2, k3;
        {
            unsigned long long kk[3];
            #pragma unroll
            for (int r = 0; r < 3; ++r) {
                int w = pw[r];
                float pt = __shfl_sync(FULL, ptot,  w & 15);
                int   lw = __shfl_sync(FULL, llast, w & 15);
                unsigned long long key = 0ULL;
                if (w >= 0) {
                    unsigned long long e = sh_srt[buf][pi[r]];
                    int c = 127 - (int)(e & 127ULL);
                    if (c != lw)   // demoted cell excluded; covered by repkey
                        key = make_key(funord((unsigned)(e >> 7)) + pt, W + w * C + c);
                }
                kk[r] = key;
            }
            k0 = kk[0]; k1 = kk[1]; k2 = kk[2];
            unsigned long long rk = __shfl_sync(FULL, repkey, lane & 15);
            k3 = (lane < W) ? staykey : rk;
        }

        // ---- exact top-16: 4x sort-32 (ILP) + 3 mirror merges
        sort32_desc(k0, lane);
        sort32_desc(k1, lane);
        sort32_desc(k2, lane);
        sort32_desc(k3, lane);
        unsigned long long m01 = merge_top16(k0, k1, lane);
        unsigned long long m23 = merge_top16(k2, k3, lane);
        unsigned long long fin = merge_top16(m01, m23, lane);   // lanes 0-15: rank-lane

        // park prefetched row
        if (t + 1 < T) {
            sh_lp[nb][lane]      = f0;
            sh_lp[nb][32 + lane] = f1;
            sh_lp[nb][64 + lane] = f2;
            if (lane < S) sh_srt[nb][lane] = sv;
        }
        __syncwarp();

        // ---- state update (all-register, shuffles from parent lanes)
        int   idx   = key_idx(fin);
        float score = key_score(fin);
        bool  is_stay = idx < W;
        int   e2 = is_stay ? 0 : (idx - W);
        int   epar = e2 / C;
        int   csym = e2 - epar * C;
        int   parent = (is_stay ? idx : epar) & 15;
        float p_spb  = __shfl_sync(FULL, spb,   parent);
        float p_spnb = __shfl_sync(FULL, spnb,  parent);
        int   p_len  = __shfl_sync(FULL, llen,  parent);
        int   p_last = __shfl_sync(FULL, llast, parent);

        bool live = lane < W;
        pb    = live ? (is_stay ? p_spb  : NEGF)        : NEGF;
        pnb   = live ? (is_stay ? p_spnb : score)       : NEGF;
        ptot  = live ? score                            : NEGF;
        llen  = live ? (is_stay ? p_len  : p_len + 1)   : 0;
        llast = live ? (is_stay ? p_last : csym)        : -1;

        if (live)
            s_bp[t][lane] = (unsigned short)((parent << 8) | (is_stay ? 0xFF : csym));
    }

    // ---- final top-P over total beam probabilities
    {
        unsigned long long key = (lane < W) ? make_key(ptot, lane) : 0ULL;
        #pragma unroll
        for (int r = 0; r < P; ++r) {
            unsigned long long v = key;
            #pragma unroll
            for (int o = 16; o; o >>= 1) {
                unsigned long long w2 = __shfl_xor_sync(FULL, v, o);
                v = (w2 > v) ? w2 : v;
            }
            if (key == v) key = 0ULL;
            int slot = key_idx(v) & 15;
            int sl = __shfl_sync(FULL, llen, slot);
            if (lane == 0) {
                s_selslot[r]  = slot;
                s_selscore[r] = key_score(v);
                s_sellen[r]   = sl;
            }
        }
    }
    __syncwarp();

    // ---- outputs (flattened float32): -scores, lens, labels
    float* o_neg = out;
    float* o_len = out + B * P;
    float* o_dec = out + 2 * B * P;

    if (lane < P) {
        o_neg[b * P + lane] = -s_selscore[lane];
        o_len[b * P + lane] = (float)s_sellen[lane];
    }
    for (int i = lane; i < P * T; i += 32)
        o_dec[(size_t)b * P * T + i] = -1.0f;
    __syncwarp();

    if (lane < P) {
        int slot = s_selslot[lane];
        int pos  = s_sellen[lane];
        float* dst = o_dec + ((size_t)b * P + lane) * T;
        for (int tt = len - 1; tt >= 0; --tt) {
            unsigned e = s_bp[tt][slot];
            int sym = e & 0xFF;
            slot    = e >> 8;
            if (sym != 0xFF) dst[--pos] = (float)sym;
        }
    }
}

extern "C" void kernel_launch(void* const* d_in, const int* in_sizes, int n_in,
                              void* d_out, int out_size) {
    const float* data = (const float*)d_in[0];
    const int*   dlen = (const int*)d_in[1];
    presort_kernel<<<(B * T + 7) / 8, 256>>>(data);
    ctc_beam_kernel<<<B, 32>>>(data, dlen, (float*)d_out);
}

// round 9
// speedup vs baseline: 1.1161x; 1.1161x over previous
#include <cuda_runtime.h>
#include <stdint.h>

#define NEGF (-1e30f)

constexpr int T = 1024;
constexpr int B = 32;
constexpr int C = 96;
constexpr int W = 16;   // beam width
constexpr int P = 4;    // top paths
constexpr int S = 21;   // top lp columns kept per (b,t); staircase needs i <= 20

// per (b,t): top-S non-blank lp columns as packed keys (ord(lp)<<7 | (127-c)), desc
__device__ unsigned long long g_sorted[(size_t)B * T * S];

// ---------- key helpers ----------
__device__ __forceinline__ unsigned ford(float f) {
    unsigned u = __float_as_uint(f);
    return (u & 0x80000000u) ? ~u : (u | 0x80000000u);
}
__device__ __forceinline__ float funord(unsigned ord) {
    unsigned u = (ord & 0x80000000u) ? (ord ^ 0x80000000u) : ~ord;
    return __uint_as_float(u);
}
// larger score wins; ties -> lower global index wins (matches jax.lax.top_k)
__device__ __forceinline__ unsigned long long make_key(float f, int idx) {
    return ((unsigned long long)ford(f) << 11) | (unsigned long long)(2047 - idx);
}
__device__ __forceinline__ int key_idx(unsigned long long k) { return 2047 - (int)(k & 2047ULL); }
__device__ __forceinline__ float key_score(unsigned long long k) { return funord((unsigned)(k >> 11)); }

__device__ __forceinline__ float lae(float a, float b) {   // jnp.logaddexp
    float m = fmaxf(a, b);
    float d = fabsf(a - b);
    return m + log1pf(expf(-d));
}

// descending bitonic sort of 32 keys across a warp (lane = index)
__device__ __forceinline__ void sort32_desc(unsigned long long& v, int lane) {
    #pragma unroll
    for (int k2 = 2; k2 <= 32; k2 <<= 1) {
        #pragma unroll
        for (int j = k2 >> 1; j > 0; j >>= 1) {
            unsigned long long o = __shfl_xor_sync(0xffffffffu, v, j);
            bool takemax = ((lane & k2) == 0) == ((lane & j) == 0);
            bool bigger  = v > o;
            v = (takemax == bigger) ? v : o;
        }
    }
}

// top-16 (sorted desc, lanes 0-15) of two lists with top-16 sorted-desc in lanes 0-15
__device__ __forceinline__ unsigned long long merge_top16(
    unsigned long long a, unsigned long long b, int lane) {
    unsigned long long brev = __shfl_sync(0xffffffffu, b, (15 - lane) & 31);
    unsigned long long v = (a > brev) ? a : brev;
    #pragma unroll
    for (int j = 8; j > 0; j >>= 1) {
        unsigned long long o = __shfl_xor_sync(0xffffffffu, v, j);
        bool takemax = ((lane & j) == 0);
        bool bigger  = v > o;
        v = (takemax == bigger) ? v : o;
    }
    return v;   // lanes 0-15 valid
}

// ============================================================================
// Kernel 1: per-(b,t) bitonic sort of non-blank lp columns, keep top-S.
// ============================================================================
__global__ __launch_bounds__(256)
void presort_kernel(const float* __restrict__ data)   // [T, B, C]
{
    int warp = (blockIdx.x * blockDim.x + threadIdx.x) >> 5;
    if (warp >= B * T) return;
    int b = warp / T, t = warp - b * T;
    int lane = threadIdx.x & 31;

    const float* row = data + ((size_t)t * B + b) * C;
    unsigned long long k[4];
    #pragma unroll
    for (int r = 0; r < 4; ++r) {
        int c = r * 32 + lane;
        if (c >= 1 && c < C)
            k[r] = ((unsigned long long)ford(row[c]) << 7) | (unsigned long long)(127 - c);
        else
            k[r] = 0ULL;
    }
    #pragma unroll
    for (int k2 = 2; k2 <= 128; k2 <<= 1) {
        #pragma unroll
        for (int j = 64; j > 0; j >>= 1) {
            if (j >= k2) continue;
            if (j >= 32) {
                int rj = j >> 5;
                #pragma unroll
                for (int r = 0; r < 4; ++r) {
                    if ((r & rj) == 0) {
                        int pr = r | rj;
                        bool desc = (((r * 32) & k2) == 0);
                        unsigned long long a = k[r], c2 = k[pr];
                        unsigned long long mx = a > c2 ? a : c2;
                        unsigned long long mn = a > c2 ? c2 : a;
                        k[r]  = desc ? mx : mn;
                        k[pr] = desc ? mn : mx;
                    }
                }
            } else {
                #pragma unroll
                for (int r = 0; r < 4; ++r) {
                    unsigned long long o = __shfl_xor_sync(0xffffffffu, k[r], j);
                    int e = r * 32 + lane;
                    bool takemax = ((e & k2) == 0) == ((lane & j) == 0);
                    bool bigger  = k[r] > o;
                    k[r] = (takemax == bigger) ? k[r] : o;
                }
            }
        }
    }
    if (lane < S)
        g_sorted[((size_t)b * T + t) * S + lane] = k[0];
}

// ============================================================================
// Kernel 2: ONE WARP per batch element. Fully register-resident: lp row in 3
// regs, sorted list in 1 u64 reg; all gathers are shuffles. ZERO sync in loop.
// ============================================================================
__global__ __launch_bounds__(32, 1)
void ctc_beam_kernel(const float* __restrict__ data,      // [T, B, C]
                     const int*   __restrict__ data_len,  // [B]
                     float*       __restrict__ out)
{
    const int b    = blockIdx.x;
    const int lane = threadIdx.x;
    const int len  = data_len[b];
    const unsigned FULL = 0xffffffffu;

    __shared__ unsigned short s_bp[T][W];                 // (parent<<8)|sym, 0xFF = stay
    __shared__ int   s_selslot[P], s_sellen[P];
    __shared__ float s_selscore[P];

    // static pool map: slot s = r*32+lane -> (w, i), staircase i <= 20/(w+1)
    // row counts {21,11,7,6,5,4,3,3,3,3,2,2,2,2,2,2} -> 78 cells; slots 78+ dead
    int pw[3], pi[3];
    {
        const int pref[17] = {0,21,32,39,45,50,54,57,60,63,66,68,70,72,74,76,78};
        #pragma unroll
        for (int r = 0; r < 3; ++r) {
            int s = r * 32 + lane;
            int w = -1, i = 0;
            #pragma unroll
            for (int ww = 0; ww < 16; ++ww)
                if (s >= pref[ww] && s < pref[ww + 1]) { w = ww; i = s - pref[ww]; }
            pw[r] = w; pi[r] = i;
        }
    }

    // row 0 into registers (lane l holds cols l, l+32, l+64; srt entry l)
    float lp0r, lp1r, lp2r;
    unsigned long long srt_cur;
    {
        const float* row0 = data + (size_t)b * C;
        lp0r = row0[lane]; lp1r = row0[32 + lane]; lp2r = row0[64 + lane];
        srt_cur = (lane < S) ? g_sorted[((size_t)b * T) * S + lane] : 0ULL;
    }

    // register beam state (lane = beam slot; high lanes carry garbage, never read)
    float pb   = (lane == 0) ? 0.0f : NEGF;
    float pnb  = NEGF;
    float ptot = lae(pb, pnb);
    int   llen = 0, llast = -1;

    for (int t = 0; t < len; ++t) {
        // prefetch row t+1 into next-regs (consumed at rotation below)
        float n0 = 0.f, n1 = 0.f, n2 = 0.f; unsigned long long nsrt = 0ULL;
        if (t + 1 < T) {
            const float* rown = data + (size_t)((t + 1) * B + b) * C;
            n0 = rown[lane]; n1 = rown[32 + lane]; n2 = rown[64 + lane];
            if (lane < S) nsrt = g_sorted[((size_t)b * T + t + 1) * S + lane];
        }

        // ---- stay / repeat candidates (lane = beam; pure shuffles, one lae)
        float lp_blank = __shfl_sync(FULL, lp0r, 0);
        int ix = (llen > 0) ? llast : 0;
        ix = (ix < 0) ? 0 : ((ix > 95) ? 0 : ix);          // garbage-lane safety
        float g0 = __shfl_sync(FULL, lp0r, ix);
        float g1 = __shfl_sync(FULL, lp1r, ix);
        float g2 = __shfl_sync(FULL, lp2r, ix);
        float lpl = (ix < 32) ? g0 : ((ix < 64) ? g1 : g2);
        float spb  = ptot + lp_blank;
        float spnb = (llen > 0) ? (pnb + lpl) : NEGF;
        unsigned long long staykey = make_key(lae(spb, spnb), lane);
        unsigned long long repkey  = (llen > 0)
            ? make_key(pb + lpl, W + lane * C + llast) : 0ULL;

        // ---- assemble pool: regs 0-2 = staircase ext cells, reg 3 = stay|rep
        unsigned long long k0, k1, k2, k3;
        {
            unsigned long long kk[3];
            #pragma unroll
            for (int r = 0; r < 3; ++r) {
                int w = pw[r];
                float pt = __shfl_sync(FULL, ptot,  w & 15);
                int   lw = __shfl_sync(FULL, llast, w & 15);
                unsigned long long e = __shfl_sync(FULL, srt_cur, pi[r]);
                int c = 127 - (int)(e & 127ULL);
                unsigned long long key = 0ULL;
                if (w >= 0 && c != lw)   // demoted cell excluded; covered by repkey
                    key = make_key(funord((unsigned)(e >> 7)) + pt, W + w * C + c);
                kk[r] = key;
            }
            k0 = kk[0]; k1 = kk[1]; k2 = kk[2];
            unsigned long long rk = __shfl_sync(FULL, repkey, lane & 15);
            k3 = (lane < W) ? staykey : rk;
        }

        // ---- exact top-16: 4x sort-32 (ILP) + 3 mirror merges
        sort32_desc(k0, lane);
        sort32_desc(k1, lane);
        sort32_desc(k2, lane);
        sort32_desc(k3, lane);
        unsigned long long m01 = merge_top16(k0, k1, lane);
        unsigned long long m23 = merge_top16(k2, k3, lane);
        unsigned long long fin = merge_top16(m01, m23, lane);   // lanes 0-15: rank-lane

        // ---- state update (all-register; high-lane garbage unread)
        int   idx   = key_idx(fin);
        float score = key_score(fin);
        bool  is_stay = idx < W;
        int   e2 = is_stay ? 0 : (idx - W);
        int   epar = e2 / C;
        int   csym = e2 - epar * C;
        int   parent = (is_stay ? idx : epar) & 15;
        float p_spb  = __shfl_sync(FULL, spb,   parent);
        float p_spnb = __shfl_sync(FULL, spnb,  parent);
        int   p_len  = __shfl_sync(FULL, llen,  parent);
        int   p_last = __shfl_sync(FULL, llast, parent);

        pb    = is_stay ? p_spb  : NEGF;
        pnb   = is_stay ? p_spnb : score;
        ptot  = score;
        llen  = is_stay ? p_len  : (p_len + 1);
        llast = is_stay ? p_last : csym;

        if (lane < W)
            s_bp[t][lane] = (unsigned short)((parent << 8) | (is_stay ? 0xFF : csym));

        // rotate register buffers (no sync needed — warp-private)
        lp0r = n0; lp1r = n1; lp2r = n2; srt_cur = nsrt;
    }

    // ---- final top-P over total beam probabilities
    {
        unsigned long long key = (lane < W) ? make_key(ptot, lane) : 0ULL;
        #pragma unroll
        for (int r = 0; r < P; ++r) {
            unsigned long long v = key;
            #pragma unroll
            for (int o = 16; o; o >>= 1) {
                unsigned long long w2 = __shfl_xor_sync(FULL, v, o);
                v = (w2 > v) ? w2 : v;
            }
            if (key == v) key = 0ULL;
            int slot = key_idx(v) & 15;
            int sl = __shfl_sync(FULL, llen, slot);
            if (lane == 0) {
                s_selslot[r]  = slot;
                s_selscore[r] = key_score(v);
                s_sellen[r]   = sl;
            }
        }
    }
    __syncwarp();

    // ---- outputs (flattened float32): -scores, lens, labels
    float* o_neg = out;
    float* o_len = out + B * P;
    float* o_dec = out + 2 * B * P;

    if (lane < P) {
        o_neg[b * P + lane] = -s_selscore[lane];
        o_len[b * P + lane] = (float)s_sellen[lane];
    }
    for (int i = lane; i < P * T; i += 32)
        o_dec[(size_t)b * P * T + i] = -1.0f;
    __syncwarp();

    if (lane < P) {
        int slot = s_selslot[lane];
        int pos  = s_sellen[lane];
        float* dst = o_dec + ((size_t)b * P + lane) * T;
        for (int tt = len - 1; tt >= 0; --tt) {
            unsigned e = s_bp[tt][slot];
            int sym = e & 0xFF;
            slot    = e >> 8;
            if (sym != 0xFF) dst[--pos] = (float)sym;
        }
    }
}

extern "C" void kernel_launch(void* const* d_in, const int* in_sizes, int n_in,
                              void* d_out, int out_size) {
    const float* data = (const float*)d_in[0];
    const int*   dlen = (const int*)d_in[1];
    presort_kernel<<<(B * T + 7) / 8, 256>>>(data);
    ctc_beam_kernel<<<B, 32>>>(data, dlen, (float*)d_out);
}